// round 2
// baseline (speedup 1.0000x reference)
#include <cuda_runtime.h>
#include <cstdint>

#define NB 4
#define NP 8192
#define CH 64
#define KNB 16
// 1/sqrt(1 + 1e-5)
#define BN_SC 0.9999950000374997f

// scratch: x after block 0  (8 MB, static device array — no allocation)
__device__ float g_x1[NB * CH * NP];

__device__ __forceinline__ unsigned long long pk2(float x, float y) {
    unsigned long long r;
    asm("mov.b64 %0, {%1, %2};" : "=l"(r) : "f"(x), "f"(y));
    return r;
}
__device__ __forceinline__ void fma2(unsigned long long& d, unsigned long long a, unsigned long long b) {
    asm("fma.rn.f32x2 %0, %1, %2, %0;" : "+l"(d) : "l"(a), "l"(b));
}
__device__ __forceinline__ void upk2(unsigned long long v, float& x, float& y) {
    asm("mov.b64 {%0, %1}, %2;" : "=f"(x), "=f"(y) : "l"(v));
}

// Dense 64->64 layer: out = [relu]( Wt^T in + bias [+ addv] )
// Wt in SMEM, layout [c][o] (transposed), so reads are warp-uniform LDS.128.
// in/out/addv are per-lane register arrays (fully unrolled indexing only!).
template <bool RELU, bool ADDIN>
__device__ __forceinline__ void layerCC(const float* __restrict__ Wt,
                                        const float* __restrict__ bias,
                                        const float* in, const float* addv, float* out) {
    unsigned long long acc[32];
#pragma unroll
    for (int i = 0; i < 32; i++) {
        float b0 = bias[2 * i], b1 = bias[2 * i + 1];
        if (ADDIN) { b0 += addv[2 * i]; b1 += addv[2 * i + 1]; }
        acc[i] = pk2(b0, b1);
    }
#pragma unroll
    for (int c = 0; c < CH; c++) {
        unsigned long long in2 = pk2(in[c], in[c]);
        const ulonglong2* wr = reinterpret_cast<const ulonglong2*>(Wt + c * CH);
#pragma unroll
        for (int i = 0; i < 16; i++) {
            ulonglong2 w = wr[i];
            fma2(acc[2 * i + 0], w.x, in2);
            fma2(acc[2 * i + 1], w.y, in2);
        }
    }
#pragma unroll
    for (int i = 0; i < 32; i++) {
        float x, y;
        upk2(acc[i], x, y);
        out[2 * i + 0] = RELU ? fmaxf(x, 0.f) : x;
        out[2 * i + 1] = RELU ? fmaxf(y, 0.f) : y;
    }
}

// One PointTransformer block (BN folded into weights at SMEM-load time).
// Warp layout: lane = half*16 + k ; the warp handles 2 consecutive points.
__global__ void __launch_bounds__(256, 1)
pt_block_kernel(const float* __restrict__ p,      // (B,3,N)
                const float* __restrict__ x_in,   // (B,C,N)
                const int* __restrict__ idx,      // (B,N,K)
                const float* __restrict__ dw1, const float* __restrict__ db1,
                const float* __restrict__ dg1, const float* __restrict__ dbe1,
                const float* __restrict__ dw2, const float* __restrict__ db2,
                const float* __restrict__ dg2, const float* __restrict__ dbe2,
                const float* __restrict__ aw1, const float* __restrict__ ab1,
                const float* __restrict__ ag1, const float* __restrict__ abe1,
                const float* __restrict__ aw2, const float* __restrict__ ab2,
                const float* __restrict__ ag2, const float* __restrict__ abe2,
                const float* __restrict__ lw, const float* __restrict__ lb,
                const float* __restrict__ lg, const float* __restrict__ lbe,
                float* __restrict__ x_out)        // (B,C,N)
{
    extern __shared__ float sm[];
    float* Wd1 = sm;            // [3][64]
    float* Wd2 = Wd1 + 192;     // [c][o]
    float* Wa1 = Wd2 + 4096;
    float* Wa2 = Wa1 + 4096;
    float* Wdn = Wa2 + 4096;
    float* Bd1 = Wdn + 4096;
    float* Bd2 = Bd1 + 64;
    float* Ba1 = Bd2 + 64;
    float* Ba2 = Ba1 + 64;
    float* Bdn = Ba2 + 64;

    const int tid = threadIdx.x;

    // Fold BN into weights: W'[o,c] = W[o,c]*g[o]*BN_SC ; b' = b*g*BN_SC + be
    for (int i = tid; i < 4096; i += 256) {
        int c = i >> 6, o = i & 63;
        Wd2[i] = dw2[o * CH + c] * (dg2[o] * BN_SC);
        Wa1[i] = aw1[o * CH + c] * (ag1[o] * BN_SC);
        Wa2[i] = aw2[o * CH + c] * (ag2[o] * BN_SC);
        Wdn[i] = lw[o * CH + c] * (lg[o] * BN_SC);
    }
    for (int i = tid; i < 192; i += 256) {
        int d = i >> 6, o = i & 63;
        Wd1[i] = dw1[o * 3 + d] * (dg1[o] * BN_SC);
    }
    if (tid < 64) {
        Bd1[tid] = db1[tid] * dg1[tid] * BN_SC + dbe1[tid];
        Bd2[tid] = db2[tid] * dg2[tid] * BN_SC + dbe2[tid];
        Ba1[tid] = ab1[tid] * ag1[tid] * BN_SC + abe1[tid];
        Ba2[tid] = ab2[tid] * ag2[tid] * BN_SC + abe2[tid];
        Bdn[tid] = lb[tid] * lg[tid] * BN_SC + lbe[tid];
    }
    __syncthreads();

    const int lane = tid & 31;
    const int half = lane >> 4;
    const int kk = lane & 15;
    const int gwarp = blockIdx.x * (blockDim.x >> 5) + (tid >> 5);
    const int nwarps = gridDim.x * (blockDim.x >> 5);
    const int npairs = NB * NP / 2;

    for (int pair = gwarp; pair < npairs; pair += nwarps) {
        int bn = pair * 2;
        int b = bn >> 13;                 // N = 8192
        int n = (bn & (NP - 1)) + half;
        const float* pb = p + b * 3 * NP;
        const float* xb = x_in + b * CH * NP;
        int j = idx[(b * NP + n) * KNB + kk];

        // gather x[:, j] early (overlaps delta layer 1)
        float gx[CH];
#pragma unroll
        for (int c = 0; c < CH; c++) gx[c] = __ldg(&xb[c * NP + j]);

        float r0 = pb[n] - pb[j];
        float r1 = pb[NP + n] - pb[NP + j];
        float r2 = pb[2 * NP + n] - pb[2 * NP + j];

        // delta layer 1 (3 -> 64), relu
        float h[CH];
#pragma unroll
        for (int co = 0; co < CH; co += 4) {
            float4 w0 = *(const float4*)&Wd1[co];
            float4 w1v = *(const float4*)&Wd1[64 + co];
            float4 w2v = *(const float4*)&Wd1[128 + co];
            float4 bb = *(const float4*)&Bd1[co];
            h[co + 0] = fmaxf(bb.x + w0.x * r0 + w1v.x * r1 + w2v.x * r2, 0.f);
            h[co + 1] = fmaxf(bb.y + w0.y * r0 + w1v.y * r1 + w2v.y * r2, 0.f);
            h[co + 2] = fmaxf(bb.z + w0.z * r0 + w1v.z * r1 + w2v.z * r2, 0.f);
            h[co + 3] = fmaxf(bb.w + w0.w * r0 + w1v.w * r1 + w2v.w * r2, 0.f);
        }

        float u[CH];
        layerCC<false, true>(Wd2, Bd2, h, gx, u);      // u = pe + gx
        layerCC<true, false>(Wa1, Ba1, u, u, h);       // h = relu(...)
        layerCC<true, false>(Wa2, Ba2, h, h, u);       // u = a (relu_last)

        // max over k (16 lanes per point)
#pragma unroll
        for (int c = 0; c < CH; c++) {
            float v = u[c];
            v = fmaxf(v, __shfl_xor_sync(0xffffffffu, v, 1));
            v = fmaxf(v, __shfl_xor_sync(0xffffffffu, v, 2));
            v = fmaxf(v, __shfl_xor_sync(0xffffffffu, v, 4));
            v = fmaxf(v, __shfl_xor_sync(0xffffffffu, v, 8));
            u[c] = v;
        }

        // down projection: lane kk computes outputs 4*kk .. 4*kk+3
        float4 ob = *(const float4*)&Bdn[4 * kk];
        float o0 = ob.x, o1 = ob.y, o2 = ob.z, o3 = ob.w;
#pragma unroll
        for (int c = 0; c < CH; c++) {
            float4 w = *(const float4*)&Wdn[c * CH + 4 * kk];
            o0 += w.x * u[c];
            o1 += w.y * u[c];
            o2 += w.z * u[c];
            o3 += w.w * u[c];
        }
        int o_idx = b * CH * NP + (4 * kk) * NP + n;
        x_out[o_idx + 0 * NP] = o0 + xb[(4 * kk + 0) * NP + n];
        x_out[o_idx + 1 * NP] = o1 + xb[(4 * kk + 1) * NP + n];
        x_out[o_idx + 2 * NP] = o2 + xb[(4 * kk + 2) * NP + n];
        x_out[o_idx + 3 * NP] = o3 + xb[(4 * kk + 3) * NP + n];
    }
}

extern "C" void kernel_launch(void* const* d_in, const int* in_sizes, int n_in,
                              void* d_out, int out_size) {
    const float* p = (const float*)d_in[0];
    const float* x = (const float*)d_in[1];
    const int* idx = (const int*)d_in[2];
    const float* w[20];
    for (int i = 0; i < 20; i++) w[i] = (const float*)d_in[3 + i];

    float* out = (float*)d_out;
    float* out_x = out + NB * 3 * NP;   // second output tensor

    // pass-through p output
    cudaMemcpyAsync(out, p, (size_t)NB * 3 * NP * sizeof(float),
                    cudaMemcpyDeviceToDevice);

    float* x1 = nullptr;
    cudaGetSymbolAddress((void**)&x1, g_x1);

    const int SMEM = (192 + 4 * 4096 + 5 * 64) * 4;  // 67584 B
    cudaFuncSetAttribute(pt_block_kernel,
                         cudaFuncAttributeMaxDynamicSharedMemorySize, SMEM);

    dim3 grid(296), blk(256);

    // per-layer weight slice sizes
    const int S_W1 = CH * 3, S_V = CH, S_W = CH * CH;

    // block 0: input_x -> g_x1
    pt_block_kernel<<<grid, blk, SMEM>>>(
        p, x, idx,
        w[0], w[1], w[2], w[3],
        w[4], w[5], w[6], w[7],
        w[8], w[9], w[10], w[11],
        w[12], w[13], w[14], w[15],
        w[16], w[17], w[18], w[19],
        x1);

    // block 1: g_x1 -> out_x  (weights at slice index 1)
    pt_block_kernel<<<grid, blk, SMEM>>>(
        p, x1, idx,
        w[0] + S_W1, w[1] + S_V, w[2] + S_V, w[3] + S_V,
        w[4] + S_W, w[5] + S_V, w[6] + S_V, w[7] + S_V,
        w[8] + S_W, w[9] + S_V, w[10] + S_V, w[11] + S_V,
        w[12] + S_W, w[13] + S_V, w[14] + S_V, w[15] + S_V,
        w[16] + S_W, w[17] + S_V, w[18] + S_V, w[19] + S_V,
        out_x);
}

// round 6
// speedup vs baseline: 1.1732x; 1.1732x over previous
#include <cuda_runtime.h>
#include <cstdint>

#define NB 4
#define NP 8192
#define CH 64
#define KNB 16
// 1/sqrt(1 + 1e-5)
#define BN_SC 0.9999950000374997f

// scratch: transposed activations x_t (B, N, C), double-buffered. 8 MB each.
__device__ __align__(16) float g_xt0[NB * NP * CH];
__device__ __align__(16) float g_xt1[NB * NP * CH];

__device__ __forceinline__ unsigned long long pk2(float x, float y) {
    unsigned long long r;
    asm("mov.b64 %0, {%1, %2};" : "=l"(r) : "f"(x), "f"(y));
    return r;
}
__device__ __forceinline__ void fma2(unsigned long long& d, unsigned long long a, unsigned long long b) {
    asm("fma.rn.f32x2 %0, %1, %2, %0;" : "+l"(d) : "l"(a), "l"(b));
}
__device__ __forceinline__ void upk2(unsigned long long v, float& x, float& y) {
    asm("mov.b64 {%0, %1}, %2;" : "=f"(x), "=f"(y) : "l"(v));
}

// Accumulate Wt^T * in into acc (acc pre-initialized), then finalize to out.
// Wt layout in SMEM: [c_in][c_out] so weight reads are warp-uniform LDS.128.
template <bool RELU>
__device__ __forceinline__ void mm_fin(const float* __restrict__ Wt,
                                       const float* in,
                                       unsigned long long* acc, float* out) {
#pragma unroll
    for (int c = 0; c < CH; c++) {
        unsigned long long in2 = pk2(in[c], in[c]);
        const ulonglong2* wr = reinterpret_cast<const ulonglong2*>(Wt + c * CH);
#pragma unroll
        for (int i = 0; i < 16; i++) {
            ulonglong2 w = wr[i];
            fma2(acc[2 * i + 0], w.x, in2);
            fma2(acc[2 * i + 1], w.y, in2);
        }
    }
#pragma unroll
    for (int i = 0; i < 32; i++) {
        float x, y;
        upk2(acc[i], x, y);
        out[2 * i + 0] = RELU ? fmaxf(x, 0.f) : x;
        out[2 * i + 1] = RELU ? fmaxf(y, 0.f) : y;
    }
}

__device__ __forceinline__ void acc_init_bias(const float* __restrict__ B,
                                              unsigned long long* acc) {
#pragma unroll
    for (int i2 = 0; i2 < 16; i2++) {
        float4 bv = *(const float4*)&B[4 * i2];
        acc[2 * i2 + 0] = pk2(bv.x, bv.y);
        acc[2 * i2 + 1] = pk2(bv.z, bv.w);
    }
}

// One PointTransformer block. x in/out in TRANSPOSED layout (B, N, C).
// Warp layout: lane = half*16 + kk ; warp handles 2 consecutive points.
__global__ void __launch_bounds__(256, 1)
pt_block_kernel(const float* __restrict__ p,      // (B,3,N)
                const float* __restrict__ xt_in,  // (B,N,C)
                const int* __restrict__ idx,      // (B,N,K)
                const float* __restrict__ dw1, const float* __restrict__ db1,
                const float* __restrict__ dg1, const float* __restrict__ dbe1,
                const float* __restrict__ dw2, const float* __restrict__ db2,
                const float* __restrict__ dg2, const float* __restrict__ dbe2,
                const float* __restrict__ aw1, const float* __restrict__ ab1,
                const float* __restrict__ ag1, const float* __restrict__ abe1,
                const float* __restrict__ aw2, const float* __restrict__ ab2,
                const float* __restrict__ ag2, const float* __restrict__ abe2,
                const float* __restrict__ lw, const float* __restrict__ lb,
                const float* __restrict__ lg, const float* __restrict__ lbe,
                float* __restrict__ xt_out)       // (B,N,C)
{
    extern __shared__ float sm[];
    float* Wd1 = sm;            // [3][64]
    float* Wd2 = Wd1 + 192;     // [c][o]
    float* Wa1 = Wd2 + 4096;
    float* Wa2 = Wa1 + 4096;
    float* Wdn = Wa2 + 4096;
    float* Bd1 = Wdn + 4096;
    float* Bd2 = Bd1 + 64;
    float* Ba1 = Bd2 + 64;
    float* Ba2 = Ba1 + 64;
    float* Bdn = Ba2 + 64;

    const int tid = threadIdx.x;

    // Fold BN into weights: W'[o,c] = W[o,c]*g[o]*BN_SC ; b' = b*g*BN_SC + be
    for (int i = tid; i < 4096; i += 256) {
        int c = i >> 6, o = i & 63;
        Wd2[i] = dw2[o * CH + c] * (dg2[o] * BN_SC);
        Wa1[i] = aw1[o * CH + c] * (ag1[o] * BN_SC);
        Wa2[i] = aw2[o * CH + c] * (ag2[o] * BN_SC);
        Wdn[i] = lw[o * CH + c] * (lg[o] * BN_SC);
    }
    for (int i = tid; i < 192; i += 256) {
        int d = i >> 6, o = i & 63;
        Wd1[i] = dw1[o * 3 + d] * (dg1[o] * BN_SC);
    }
    if (tid < 64) {
        Bd1[tid] = db1[tid] * dg1[tid] * BN_SC + dbe1[tid];
        Bd2[tid] = db2[tid] * dg2[tid] * BN_SC + dbe2[tid];
        Ba1[tid] = ab1[tid] * ag1[tid] * BN_SC + abe1[tid];
        Ba2[tid] = ab2[tid] * ag2[tid] * BN_SC + abe2[tid];
        Bdn[tid] = lb[tid] * lg[tid] * BN_SC + lbe[tid];
    }
    __syncthreads();

    const int lane = tid & 31;
    const int half = lane >> 4;
    const int kk = lane & 15;
    const int gwarp = blockIdx.x * (blockDim.x >> 5) + (tid >> 5);
    const int nwarps = gridDim.x * (blockDim.x >> 5);
    const int npairs = NB * NP / 2;

    for (int pair = gwarp; pair < npairs; pair += nwarps) {
        int bn = pair * 2;
        int b = bn >> 13;                 // N = 8192
        int n = (bn & (NP - 1)) + half;
        const float* pb = p + b * 3 * NP;
        int j = idx[(b * NP + n) * KNB + kk];

        // gather x_t[j, :] — 16 contiguous float4 loads (overlap with delta1)
        const float4* gxr = (const float4*)(xt_in + ((size_t)(b * NP + j)) * CH);
        float4 gxv[16];
#pragma unroll
        for (int i2 = 0; i2 < 16; i2++) gxv[i2] = __ldg(gxr + i2);

        float r0 = pb[n] - pb[j];
        float r1 = pb[NP + n] - pb[NP + j];
        float r2 = pb[2 * NP + n] - pb[2 * NP + j];

        // delta layer 1 (3 -> 64), relu
        float h[CH];
#pragma unroll
        for (int co = 0; co < CH; co += 4) {
            float4 w0 = *(const float4*)&Wd1[co];
            float4 w1v = *(const float4*)&Wd1[64 + co];
            float4 w2v = *(const float4*)&Wd1[128 + co];
            float4 bb = *(const float4*)&Bd1[co];
            h[co + 0] = fmaxf(bb.x + w0.x * r0 + w1v.x * r1 + w2v.x * r2, 0.f);
            h[co + 1] = fmaxf(bb.y + w0.y * r0 + w1v.y * r1 + w2v.y * r2, 0.f);
            h[co + 2] = fmaxf(bb.z + w0.z * r0 + w1v.z * r1 + w2v.z * r2, 0.f);
            h[co + 3] = fmaxf(bb.w + w0.w * r0 + w1v.w * r1 + w2v.w * r2, 0.f);
        }

        // layer 2: u = Wd2*h + b + gx   (gx folded into acc init — no gx regs)
        unsigned long long acc[32];
#pragma unroll
        for (int i2 = 0; i2 < 16; i2++) {
            float4 bv = *(const float4*)&Bd2[4 * i2];
            acc[2 * i2 + 0] = pk2(bv.x + gxv[i2].x, bv.y + gxv[i2].y);
            acc[2 * i2 + 1] = pk2(bv.z + gxv[i2].z, bv.w + gxv[i2].w);
        }
        float u[CH];
        mm_fin<false>(Wd2, h, acc, u);

        // layer 3: h = relu(Wa1*u + b)
        acc_init_bias(Ba1, acc);
        mm_fin<true>(Wa1, u, acc, h);

        // layer 4: u = relu(Wa2*h + b)
        acc_init_bias(Ba2, acc);
        mm_fin<true>(Wa2, h, acc, u);

        // max over k (16 lanes per point)
#pragma unroll
        for (int c = 0; c < CH; c++) {
            float v = u[c];
            v = fmaxf(v, __shfl_xor_sync(0xffffffffu, v, 1));
            v = fmaxf(v, __shfl_xor_sync(0xffffffffu, v, 2));
            v = fmaxf(v, __shfl_xor_sync(0xffffffffu, v, 4));
            v = fmaxf(v, __shfl_xor_sync(0xffffffffu, v, 8));
            u[c] = v;
        }

        // down projection: lane kk computes outputs 4*kk .. 4*kk+3
        float4 ob = *(const float4*)&Bdn[4 * kk];
        float o0 = ob.x, o1 = ob.y, o2 = ob.z, o3 = ob.w;
#pragma unroll
        for (int c = 0; c < CH; c++) {
            float4 w = *(const float4*)&Wdn[c * CH + 4 * kk];
            o0 += w.x * u[c];
            o1 += w.y * u[c];
            o2 += w.z * u[c];
            o3 += w.w * u[c];
        }
        // residual (coalesced float4) + coalesced float4 store
        size_t row = ((size_t)(b * NP + n)) * CH;
        float4 res = __ldg((const float4*)(xt_in + row) + kk);
        float4 o;
        o.x = o0 + res.x; o.y = o1 + res.y; o.z = o2 + res.z; o.w = o3 + res.w;
        *((float4*)(xt_out + row) + kk) = o;
    }
}

// (B,C,N) -> (B,N,C) tiled transpose
__global__ void transpose_cn_nc(const float* __restrict__ in, float* __restrict__ out) {
    __shared__ float t[32][33];
    int b = blockIdx.z;
    int c0 = blockIdx.y * 32;
    int n0 = blockIdx.x * 32;
    int tx = threadIdx.x, ty = threadIdx.y;
#pragma unroll
    for (int i = ty; i < 32; i += 8)
        t[i][tx] = in[((size_t)b * CH + c0 + i) * NP + n0 + tx];
    __syncthreads();
#pragma unroll
    for (int i = ty; i < 32; i += 8)
        out[((size_t)b * NP + n0 + i) * CH + c0 + tx] = t[tx][i];
}

// (B,N,C) -> (B,C,N) tiled transpose
__global__ void transpose_nc_cn(const float* __restrict__ in, float* __restrict__ out) {
    __shared__ float t[32][33];
    int b = blockIdx.z;
    int n0 = blockIdx.y * 32;
    int c0 = blockIdx.x * 32;
    int tx = threadIdx.x, ty = threadIdx.y;
    // read: t[n_local][c_local]
#pragma unroll
    for (int i = ty; i < 32; i += 8)
        t[i][tx] = in[((size_t)b * NP + n0 + i) * CH + c0 + tx];
    __syncthreads();
    // write element (c = c0+i, n = n0+tx) = in[n0+tx][c0+i] = t[tx][i]   (FIXED)
#pragma unroll
    for (int i = ty; i < 32; i += 8)
        out[((size_t)b * CH + c0 + i) * NP + n0 + tx] = t[tx][i];
}

extern "C" void kernel_launch(void* const* d_in, const int* in_sizes, int n_in,
                              void* d_out, int out_size) {
    const float* p = (const float*)d_in[0];
    const float* x = (const float*)d_in[1];
    const int* idx = (const int*)d_in[2];
    const float* w[20];
    for (int i = 0; i < 20; i++) w[i] = (const float*)d_in[3 + i];

    float* out = (float*)d_out;
    float* out_x = out + NB * 3 * NP;   // second output tensor

    // pass-through p output
    cudaMemcpyAsync(out, p, (size_t)NB * 3 * NP * sizeof(float),
                    cudaMemcpyDeviceToDevice);

    float *xt0 = nullptr, *xt1 = nullptr;
    cudaGetSymbolAddress((void**)&xt0, g_xt0);
    cudaGetSymbolAddress((void**)&xt1, g_xt1);

    const int SMEM = (192 + 4 * 4096 + 5 * 64) * 4;  // 67584 B
    cudaFuncSetAttribute(pt_block_kernel,
                         cudaFuncAttributeMaxDynamicSharedMemorySize, SMEM);

    dim3 tgrid(NP / 32, CH / 32, NB), tblk(32, 8);
    // transpose input x to (B,N,C)
    transpose_cn_nc<<<tgrid, tblk>>>(x, xt0);

    dim3 grid(296), blk(256);
    const int S_W1 = CH * 3, S_V = CH, S_W = CH * CH;

    // block 0: xt0 -> xt1
    pt_block_kernel<<<grid, blk, SMEM>>>(
        p, xt0, idx,
        w[0], w[1], w[2], w[3],
        w[4], w[5], w[6], w[7],
        w[8], w[9], w[10], w[11],
        w[12], w[13], w[14], w[15],
        w[16], w[17], w[18], w[19],
        xt1);

    // block 1: xt1 -> xt0 (weights at slice index 1)
    pt_block_kernel<<<grid, blk, SMEM>>>(
        p, xt1, idx,
        w[0] + S_W1, w[1] + S_V, w[2] + S_V, w[3] + S_V,
        w[4] + S_W, w[5] + S_V, w[6] + S_V, w[7] + S_V,
        w[8] + S_W, w[9] + S_V, w[10] + S_V, w[11] + S_V,
        w[12] + S_W, w[13] + S_V, w[14] + S_V, w[15] + S_V,
        w[16] + S_W, w[17] + S_V, w[18] + S_V, w[19] + S_V,
        xt0);

    // un-transpose to (B,C,N) output
    dim3 tgrid2(CH / 32, NP / 32, NB);
    transpose_nc_cn<<<tgrid2, tblk>>>(xt0, out_x);
}